// round 2
// baseline (speedup 1.0000x reference)
#include <cuda_runtime.h>
#include <math.h>

#define N_TOK   8192
#define EDIM    256
#define NE      8192
#define BATCH   8
#define HW      1024
#define BM      64
#define BN      64
#define SLDA    68      // padded floats per k-row: 68*4B = 272B, 16B-aligned

// ---- scratch (no allocation allowed) ----
__device__ __align__(16) float g_zf[N_TOK * EDIM];   // z in [token][dim] layout
__device__ int   g_idx[N_TOK];
__device__ float g_msePart[BATCH * 256];

// ------------------------------------------------------------------
// K1: NCHW -> [token][dim] transpose (per batch: [256 c][1024 hw] -> [1024][256])
// ------------------------------------------------------------------
__global__ void k_transpose(const float* __restrict__ z) {
    __shared__ float tile[32][33];
    const int b = blockIdx.z;
    const int hwBase = blockIdx.x * 32;
    const int cBase  = blockIdx.y * 32;
    const int tx = threadIdx.x, ty = threadIdx.y;   // 32 x 8
#pragma unroll
    for (int j = 0; j < 4; j++) {
        int c = cBase + ty + 8 * j;
        tile[ty + 8 * j][tx] = z[(b * EDIM + c) * HW + hwBase + tx];
    }
    __syncthreads();
#pragma unroll
    for (int j = 0; j < 4; j++) {
        int hw = hwBase + ty + 8 * j;
        g_zf[(b * HW + hw) * EDIM + cBase + tx] = tile[tx][ty + 8 * j];
    }
}

// ------------------------------------------------------------------
// K2: fused SGEMM + row argmin.
// Grid: 128 CTAs (BM=64 rows each), each CTA loops over all 8192 codes.
// score_k = fmaf(-2, dot, zn_row)  (replicates reference rounding exactly:
// rn(zn + en) == zn since en < half-ulp(zn); ties broken by FIRST index).
// ------------------------------------------------------------------
__global__ void __launch_bounds__(256, 1) k_argmin(const float* __restrict__ emb) {
    extern __shared__ float sm[];
    float* As   = sm;                       // [256][SLDA] k-major
    float* Bs   = As + 256 * SLDA;          // [256][SLDA] k-major
    float* zn   = Bs + 256 * SLDA;          // [64]
    float* redV = zn + BM;                  // [64][16]
    int*   redI = (int*)(redV + BM * 16);   // [64][16]

    const int tid = threadIdx.x;
    const int tx = tid & 15, ty = tid >> 4;     // 16 x 16, 4x4 per thread
    const int rowBase = blockIdx.x * BM;

    // Load A tile (64 x 256) into k-major smem
#pragma unroll
    for (int it = 0; it < 16; it++) {
        int lin = it * 256 + tid;           // float4 index, 0..4095
        int r  = lin >> 6;                  // 64 float4 per row
        int c4 = lin & 63;
        float4 v = *(const float4*)&g_zf[(rowBase + r) * EDIM + c4 * 4];
        As[(c4 * 4 + 0) * SLDA + r] = v.x;
        As[(c4 * 4 + 1) * SLDA + r] = v.y;
        As[(c4 * 4 + 2) * SLDA + r] = v.z;
        As[(c4 * 4 + 3) * SLDA + r] = v.w;
    }
    __syncthreads();

    // per-row ||z||^2 (any fp32 order: score grid is shift-invariant per binade)
    if (tid < BM) {
        float s = 0.f;
        for (int k = 0; k < EDIM; k++) {
            float a = As[k * SLDA + tid];
            s = fmaf(a, a, s);
        }
        zn[tid] = s;
    }

    float bestV[4];
    int   bestI[4];
#pragma unroll
    for (int i = 0; i < 4; i++) { bestV[i] = __int_as_float(0x7f800000); bestI[i] = 0; }

    float zrow[4];
    bool zloaded = false;

    for (int t = 0; t < NE / BN; t++) {
        __syncthreads();    // Bs (and first time: zn) ready-to-overwrite / ready-to-read
        if (!zloaded) {
#pragma unroll
            for (int i = 0; i < 4; i++) zrow[i] = zn[ty * 4 + i];
            zloaded = true;
        }
        // Load B tile (64 codes x 256) into k-major smem
#pragma unroll
        for (int it = 0; it < 16; it++) {
            int lin = it * 256 + tid;
            int r  = lin >> 6;
            int c4 = lin & 63;
            float4 v = __ldg((const float4*)&emb[(t * BN + r) * EDIM + c4 * 4]);
            Bs[(c4 * 4 + 0) * SLDA + r] = v.x;
            Bs[(c4 * 4 + 1) * SLDA + r] = v.y;
            Bs[(c4 * 4 + 2) * SLDA + r] = v.z;
            Bs[(c4 * 4 + 3) * SLDA + r] = v.w;
        }
        __syncthreads();

        float acc[4][4];
#pragma unroll
        for (int i = 0; i < 4; i++)
#pragma unroll
            for (int j = 0; j < 4; j++) acc[i][j] = 0.f;

#pragma unroll 8
        for (int k = 0; k < EDIM; k++) {
            const float4 a  = *(const float4*)(As + k * SLDA + (ty << 2));
            const float4 bv = *(const float4*)(Bs + k * SLDA + (tx << 2));
            acc[0][0] = fmaf(a.x, bv.x, acc[0][0]);
            acc[0][1] = fmaf(a.x, bv.y, acc[0][1]);
            acc[0][2] = fmaf(a.x, bv.z, acc[0][2]);
            acc[0][3] = fmaf(a.x, bv.w, acc[0][3]);
            acc[1][0] = fmaf(a.y, bv.x, acc[1][0]);
            acc[1][1] = fmaf(a.y, bv.y, acc[1][1]);
            acc[1][2] = fmaf(a.y, bv.z, acc[1][2]);
            acc[1][3] = fmaf(a.y, bv.w, acc[1][3]);
            acc[2][0] = fmaf(a.z, bv.x, acc[2][0]);
            acc[2][1] = fmaf(a.z, bv.y, acc[2][1]);
            acc[2][2] = fmaf(a.z, bv.z, acc[2][2]);
            acc[2][3] = fmaf(a.z, bv.w, acc[2][3]);
            acc[3][0] = fmaf(a.w, bv.x, acc[3][0]);
            acc[3][1] = fmaf(a.w, bv.y, acc[3][1]);
            acc[3][2] = fmaf(a.w, bv.z, acc[3][2]);
            acc[3][3] = fmaf(a.w, bv.w, acc[3][3]);
        }

        // argmin epilogue (ascending col order within thread; strict < keeps first)
        const int colBase = t * BN + tx * 4;
#pragma unroll
        for (int i = 0; i < 4; i++) {
            const float z = zrow[i];
#pragma unroll
            for (int j = 0; j < 4; j++) {
                float s = fmaf(-2.0f, acc[i][j], z);
                if (s < bestV[i]) { bestV[i] = s; bestI[i] = colBase + j; }
            }
        }
    }

    __syncthreads();
#pragma unroll
    for (int i = 0; i < 4; i++) {
        redV[(ty * 4 + i) * 16 + tx] = bestV[i];
        redI[(ty * 4 + i) * 16 + tx] = bestI[i];
    }
    __syncthreads();
    if (tid < BM) {
        float bv = redV[tid * 16 + 0];
        int   bi = redI[tid * 16 + 0];
        for (int x = 1; x < 16; x++) {
            float v = redV[tid * 16 + x];
            int   ii = redI[tid * 16 + x];
            if (v < bv || (v == bv && ii < bi)) { bv = v; bi = ii; }
        }
        g_idx[rowBase + tid] = bi;
    }
}

// ------------------------------------------------------------------
// K3: gather z_q into NCHW output + per-(batch,channel) MSE partials
// grid (256 c, 8 b), 256 threads, 4 hw each -> coalesced writes
// ------------------------------------------------------------------
__global__ void k_gather(const float* __restrict__ emb,
                         const float* __restrict__ z,
                         float* __restrict__ out) {
    const int c = blockIdx.x;
    const int b = blockIdx.y;
    const int tid = threadIdx.x;
    float lsum = 0.f;
#pragma unroll
    for (int u = 0; u < 4; u++) {
        int hw = u * 256 + tid;
        int n  = b * HW + hw;
        int k  = g_idx[n];
        float e  = __ldg(&emb[k * EDIM + c]);
        float zv = z[(b * EDIM + c) * HW + hw];
        out[(b * EDIM + c) * HW + hw] = e;
        float d = e - zv;
        lsum = fmaf(d, d, lsum);
    }
    __shared__ float red[256];
    red[tid] = lsum;
    __syncthreads();
    for (int s = 128; s > 0; s >>= 1) {
        if (tid < s) red[tid] += red[tid + s];
        __syncthreads();
    }
    if (tid == 0) g_msePart[b * 256 + c] = red[0];
}

// ------------------------------------------------------------------
// K4: losses, idx->float, histogram (in smem, re-zeroed every call), perplexity
// ------------------------------------------------------------------
__global__ void k_finalize(float* __restrict__ out) {
    __shared__ int   counts[NE];    // 32 KB
    __shared__ float redf[256];
    __shared__ float mseS[BATCH];
    const int tid = threadIdx.x;

    for (int i = tid; i < NE; i += 256) counts[i] = 0;
    __syncthreads();

    for (int i = tid; i < N_TOK; i += 256) {
        int k = g_idx[i];
        out[2097160 + i] = (float)k;
        atomicAdd(&counts[k], 1);
    }

    // per-batch MSE sums
    for (int b = 0; b < BATCH; b++) {
        redf[tid] = g_msePart[b * 256 + tid];
        __syncthreads();
        for (int s = 128; s > 0; s >>= 1) {
            if (tid < s) redf[tid] += redf[tid + s];
            __syncthreads();
        }
        if (tid == 0) mseS[b] = redf[0];
        __syncthreads();
    }

    if (tid < BATCH) {
        float m = mseS[tid] * (1.0f / 262144.0f);   // mean over (H,W,C)
        out[2097152 + tid] = m + 0.25f * m;         // emb_loss + beta*commit_loss
    }
    if (tid == 0) {
        float tot = 0.f;
        for (int b = 0; b < BATCH; b++) tot += mseS[b] * (1.0f / 262144.0f);
        float cm = tot * (1.0f / 8.0f);
        out[2105352] = cm;           // mean(commit_loss)
        out[2105353] = 0.25f * cm;   // beta * mean(emb_loss)
    }
    __syncthreads();

    // perplexity
    float ps = 0.f;
    for (int i = tid; i < NE; i += 256) {
        float p = (float)counts[i] * (1.0f / 8192.0f);
        ps += p * logf(p + 1e-10f);
    }
    redf[tid] = ps;
    __syncthreads();
    for (int s = 128; s > 0; s >>= 1) {
        if (tid < s) redf[tid] += redf[tid + s];
        __syncthreads();
    }
    if (tid == 0) out[2105354] = expf(-redf[0]);
}

// ------------------------------------------------------------------
extern "C" void kernel_launch(void* const* d_in, const int* in_sizes, int n_in,
                              void* d_out, int out_size) {
    const float* z   = (const float*)d_in[0];   // [8,256,32,32]
    const float* emb = (const float*)d_in[1];   // [8192,256]
    float* out = (float*)d_out;

    // 147,712 B dynamic smem for the GEMM kernel (opt-in; idempotent)
    static const int smemBytes = (256 * SLDA * 2 + BM + BM * 16 * 2) * 4;
    cudaFuncSetAttribute(k_argmin, cudaFuncAttributeMaxDynamicSharedMemorySize, smemBytes);

    dim3 tb(32, 8);
    dim3 tg(HW / 32, EDIM / 32, BATCH);
    k_transpose<<<tg, tb>>>(z);

    k_argmin<<<N_TOK / BM, 256, smemBytes>>>(emb);

    dim3 gg(EDIM, BATCH);
    k_gather<<<gg, 256>>>(emb, z, out);

    k_finalize<<<1, 256>>>(out);
}

// round 3
// speedup vs baseline: 1.1514x; 1.1514x over previous
#include <cuda_runtime.h>
#include <math.h>

#define N_TOK   8192
#define EDIM    256
#define NE      8192
#define BATCH   8
#define HW      1024
#define BM      64
#define BN      128
#define SLDA    68      // A row pitch in floats (272B, 16B-aligned)
#define SLDB    132     // B row pitch in floats (528B, 16B-aligned)

typedef unsigned long long ull;

// ---- scratch (no allocation allowed) ----
__device__ __align__(16) float g_zf[N_TOK * EDIM];   // z in [token][dim] layout
__device__ int   g_idx[N_TOK];
__device__ float g_msePart[BATCH * 256];

// ---- packed fp32x2 helpers (bitwise == two scalar IEEE fp32 FMAs) ----
__device__ __forceinline__ ull pack2(float lo, float hi) {
    ull r; asm("mov.b64 %0,{%1,%2};" : "=l"(r) : "f"(lo), "f"(hi)); return r;
}
__device__ __forceinline__ void unpack2(ull v, float& lo, float& hi) {
    asm("mov.b64 {%0,%1},%2;" : "=f"(lo), "=f"(hi) : "l"(v));
}
__device__ __forceinline__ void fma2_acc(ull& d, ull a, ull b) {
    asm("fma.rn.f32x2 %0,%1,%2,%0;" : "+l"(d) : "l"(a), "l"(b));
}
__device__ __forceinline__ ull fma2(ull a, ull b, ull c) {
    ull d; asm("fma.rn.f32x2 %0,%1,%2,%3;" : "=l"(d) : "l"(a), "l"(b), "l"(c)); return d;
}

// ------------------------------------------------------------------
// K1: NCHW -> [token][dim] transpose
// ------------------------------------------------------------------
__global__ void k_transpose(const float* __restrict__ z) {
    __shared__ float tile[32][33];
    const int b = blockIdx.z;
    const int hwBase = blockIdx.x * 32;
    const int cBase  = blockIdx.y * 32;
    const int tx = threadIdx.x, ty = threadIdx.y;   // 32 x 8
#pragma unroll
    for (int j = 0; j < 4; j++) {
        int c = cBase + ty + 8 * j;
        tile[ty + 8 * j][tx] = z[(b * EDIM + c) * HW + hwBase + tx];
    }
    __syncthreads();
#pragma unroll
    for (int j = 0; j < 4; j++) {
        int hw = hwBase + ty + 8 * j;
        g_zf[(b * HW + hw) * EDIM + cBase + tx] = tile[tx][ty + 8 * j];
    }
}

// ------------------------------------------------------------------
// K2: fused SGEMM + row argmin, packed fp32x2 FFMA micro-kernel.
// 128 CTAs (BM=64 rows each) loop over 64 tiles of BN=128 codes.
// score = fmaf(-2, dot, zn); first-index tie break (strict <, ascending cols).
// ------------------------------------------------------------------
__global__ void __launch_bounds__(256, 1) k_argmin(const float* __restrict__ emb) {
    extern __shared__ float sm[];
    float* As   = sm;                        // [256][SLDA] k-major
    float* Bs   = As + 256 * SLDA;           // [256][SLDB] k-major
    float* zn   = Bs + 256 * SLDB;           // [64]
    float* redV = zn + BM;                   // [64][16]
    int*   redI = (int*)(redV + BM * 16);    // [64][16]

    const int tid = threadIdx.x;
    const int tx = tid & 15, ty = tid >> 4;  // 16 x 16
    const int rowBase = blockIdx.x * BM;

    // Load A tile (64 x 256) into k-major smem
#pragma unroll
    for (int it = 0; it < 16; it++) {
        int lin = it * 256 + tid;            // float4 index
        int r  = lin >> 6;
        int c4 = lin & 63;
        float4 v = *(const float4*)&g_zf[(rowBase + r) * EDIM + c4 * 4];
        As[(c4 * 4 + 0) * SLDA + r] = v.x;
        As[(c4 * 4 + 1) * SLDA + r] = v.y;
        As[(c4 * 4 + 2) * SLDA + r] = v.z;
        As[(c4 * 4 + 3) * SLDA + r] = v.w;
    }
    __syncthreads();

    // per-row ||z||^2 (shift grid is reorder-invariant within a binade)
    if (tid < BM) {
        float s = 0.f;
        for (int k = 0; k < EDIM; k++) {
            float a = As[k * SLDA + tid];
            s = fmaf(a, a, s);
        }
        zn[tid] = s;
    }

    float bestV[4];
    int   bestI[4];
#pragma unroll
    for (int i = 0; i < 4; i++) { bestV[i] = __int_as_float(0x7f800000); bestI[i] = 0; }

    ull zz[4];
    bool zloaded = false;
    const ull neg2 = pack2(-2.0f, -2.0f);

    const float* Ap = As + (ty << 2);
    const float* Bp = Bs + (tx << 2);

    for (int t = 0; t < NE / BN; t++) {
        __syncthreads();    // Bs free to overwrite (and zn ready on first pass)
        if (!zloaded) {
#pragma unroll
            for (int i = 0; i < 4; i++) { float z = zn[(ty << 2) + i]; zz[i] = pack2(z, z); }
            zloaded = true;
        }
        // Load B tile (128 codes x 256) into k-major smem
#pragma unroll
        for (int it = 0; it < 32; it++) {
            int lin = it * 256 + tid;        // float4 index, 0..8191
            int r  = lin >> 6;               // code row 0..127
            int c4 = lin & 63;
            float4 v = __ldg((const float4*)&emb[(t * BN + r) * EDIM + c4 * 4]);
            Bs[(c4 * 4 + 0) * SLDB + r] = v.x;
            Bs[(c4 * 4 + 1) * SLDB + r] = v.y;
            Bs[(c4 * 4 + 2) * SLDB + r] = v.z;
            Bs[(c4 * 4 + 3) * SLDB + r] = v.w;
        }
        __syncthreads();

        // acc[i][p]: row i (ty*4+i), col-pair p: p0=(c0,c0+1) p1=(c0+2,c0+3)
        //                                         p2=(c1,c1+1) p3=(c1+2,c1+3)
        ull acc[4][4];
#pragma unroll
        for (int i = 0; i < 4; i++)
#pragma unroll
            for (int p = 0; p < 4; p++) acc[i][p] = 0ULL;

#pragma unroll 8
        for (int k = 0; k < EDIM; k++) {
            const float4 a = *(const float4*)(Ap + k * SLDA);
            ull ad0 = pack2(a.x, a.x);
            ull ad1 = pack2(a.y, a.y);
            ull ad2 = pack2(a.z, a.z);
            ull ad3 = pack2(a.w, a.w);
            const ulonglong2 bg0 = *(const ulonglong2*)(Bp + k * SLDB);       // cols tx*4..+3
            const ulonglong2 bg1 = *(const ulonglong2*)(Bp + k * SLDB + 64);  // cols 64+tx*4..+3
            fma2_acc(acc[0][0], ad0, bg0.x); fma2_acc(acc[0][1], ad0, bg0.y);
            fma2_acc(acc[0][2], ad0, bg1.x); fma2_acc(acc[0][3], ad0, bg1.y);
            fma2_acc(acc[1][0], ad1, bg0.x); fma2_acc(acc[1][1], ad1, bg0.y);
            fma2_acc(acc[1][2], ad1, bg1.x); fma2_acc(acc[1][3], ad1, bg1.y);
            fma2_acc(acc[2][0], ad2, bg0.x); fma2_acc(acc[2][1], ad2, bg0.y);
            fma2_acc(acc[2][2], ad2, bg1.x); fma2_acc(acc[2][3], ad2, bg1.y);
            fma2_acc(acc[3][0], ad3, bg0.x); fma2_acc(acc[3][1], ad3, bg0.y);
            fma2_acc(acc[3][2], ad3, bg1.x); fma2_acc(acc[3][3], ad3, bg1.y);
        }

        // argmin epilogue: ascending global col order + strict < => first index
        const int c0 = t * BN + (tx << 2);
        const int c1 = t * BN + 64 + (tx << 2);
#pragma unroll
        for (int i = 0; i < 4; i++) {
#pragma unroll
            for (int p = 0; p < 4; p++) {
                ull s2 = fma2(neg2, acc[i][p], zz[i]);
                float lo, hi; unpack2(s2, lo, hi);
                int base = ((p < 2) ? c0 : c1) + ((p & 1) << 1);
                if (lo < bestV[i]) { bestV[i] = lo; bestI[i] = base; }
                if (hi < bestV[i]) { bestV[i] = hi; bestI[i] = base + 1; }
            }
        }
    }

    __syncthreads();
#pragma unroll
    for (int i = 0; i < 4; i++) {
        redV[((ty << 2) + i) * 16 + tx] = bestV[i];
        redI[((ty << 2) + i) * 16 + tx] = bestI[i];
    }
    __syncthreads();
    if (tid < BM) {
        float bv = redV[tid * 16 + 0];
        int   bi = redI[tid * 16 + 0];
        for (int x = 1; x < 16; x++) {
            float v  = redV[tid * 16 + x];
            int   ii = redI[tid * 16 + x];
            if (v < bv || (v == bv && ii < bi)) { bv = v; bi = ii; }
        }
        g_idx[rowBase + tid] = bi;
    }
}

// ------------------------------------------------------------------
// K3: gather z_q into NCHW output + per-(batch,channel) MSE partials
// ------------------------------------------------------------------
__global__ void k_gather(const float* __restrict__ emb,
                         const float* __restrict__ z,
                         float* __restrict__ out) {
    const int c = blockIdx.x;
    const int b = blockIdx.y;
    const int tid = threadIdx.x;
    float lsum = 0.f;
#pragma unroll
    for (int u = 0; u < 4; u++) {
        int hw = u * 256 + tid;
        int n  = b * HW + hw;
        int k  = g_idx[n];
        float e  = __ldg(&emb[k * EDIM + c]);
        float zv = z[(b * EDIM + c) * HW + hw];
        out[(b * EDIM + c) * HW + hw] = e;
        float d = e - zv;
        lsum = fmaf(d, d, lsum);
    }
    __shared__ float red[256];
    red[tid] = lsum;
    __syncthreads();
    for (int s = 128; s > 0; s >>= 1) {
        if (tid < s) red[tid] += red[tid + s];
        __syncthreads();
    }
    if (tid == 0) g_msePart[b * 256 + c] = red[0];
}

// ------------------------------------------------------------------
// K4: losses, idx->float, histogram, perplexity
// ------------------------------------------------------------------
__global__ void k_finalize(float* __restrict__ out) {
    __shared__ int   counts[NE];
    __shared__ float redf[256];
    __shared__ float mseS[BATCH];
    const int tid = threadIdx.x;

    for (int i = tid; i < NE; i += 256) counts[i] = 0;
    __syncthreads();

    for (int i = tid; i < N_TOK; i += 256) {
        int k = g_idx[i];
        out[2097160 + i] = (float)k;
        atomicAdd(&counts[k], 1);
    }

    for (int b = 0; b < BATCH; b++) {
        redf[tid] = g_msePart[b * 256 + tid];
        __syncthreads();
        for (int s = 128; s > 0; s >>= 1) {
            if (tid < s) redf[tid] += redf[tid + s];
            __syncthreads();
        }
        if (tid == 0) mseS[b] = redf[0];
        __syncthreads();
    }

    if (tid < BATCH) {
        float m = mseS[tid] * (1.0f / 262144.0f);
        out[2097152 + tid] = m + 0.25f * m;
    }
    if (tid == 0) {
        float tot = 0.f;
        for (int b = 0; b < BATCH; b++) tot += mseS[b] * (1.0f / 262144.0f);
        float cm = tot * (1.0f / 8.0f);
        out[2105352] = cm;
        out[2105353] = 0.25f * cm;
    }
    __syncthreads();

    float ps = 0.f;
    for (int i = tid; i < NE; i += 256) {
        float p = (float)counts[i] * (1.0f / 8192.0f);
        ps += p * logf(p + 1e-10f);
    }
    redf[tid] = ps;
    __syncthreads();
    for (int s = 128; s > 0; s >>= 1) {
        if (tid < s) redf[tid] += redf[tid + s];
        __syncthreads();
    }
    if (tid == 0) out[2105354] = expf(-redf[0]);
}

// ------------------------------------------------------------------
extern "C" void kernel_launch(void* const* d_in, const int* in_sizes, int n_in,
                              void* d_out, int out_size) {
    const float* z   = (const float*)d_in[0];   // [8,256,32,32]
    const float* emb = (const float*)d_in[1];   // [8192,256]
    float* out = (float*)d_out;

    static const int smemBytes = (256 * SLDA + 256 * SLDB + BM + BM * 16 * 2) * 4;
    cudaFuncSetAttribute(k_argmin, cudaFuncAttributeMaxDynamicSharedMemorySize, smemBytes);

    dim3 tb(32, 8);
    dim3 tg(HW / 32, EDIM / 32, BATCH);
    k_transpose<<<tg, tb>>>(z);

    k_argmin<<<N_TOK / BM, 256, smemBytes>>>(emb);

    dim3 gg(EDIM, BATCH);
    k_gather<<<gg, 256>>>(emb, z, out);

    k_finalize<<<1, 256>>>(out);
}

// round 5
// speedup vs baseline: 3.2155x; 2.7928x over previous
#include <cuda_runtime.h>
#include <math.h>
#include <stdint.h>

#define N_TOK   8192
#define EDIM    256
#define NE      8192
#define BATCH   8
#define HW      1024

#define MT      64                  // tokens per CTA -> 128 CTAs
#define WN      1024                // codes per warp (8 warps disjoint)
#define NCHUNK  32                  // n32 chunks per warp
#define KPAIRS  16                  // 32 k-steps of 8, paired
#define EPS     6.5e-5f             // >= 2 score-grid ulps (zn<512)
#define CAP     32

typedef unsigned long long ull;

// ---- scratch (static device globals; no allocation) ----
__device__ __align__(16) float g_zf[N_TOK * EDIM];          // z [token][dim]
__device__ __align__(16) uint4 g_embF[NE / 8 * KPAIRS * 32]; // emb in tf32 frag layout
__device__ ull   g_cand[N_TOK * 8 * 4 * CAP];               // (scoreBits<<32)|idx appends
__device__ ull   g_best[N_TOK];                             // packed exact best
__device__ float g_msePart[BATCH * 256];

__device__ __forceinline__ uint32_t f2tf32(float x) {
    uint32_t r; asm("cvt.rna.tf32.f32 %0,%1;" : "=r"(r) : "f"(x)); return r;
}
__device__ __forceinline__ void mma_tf32(float* d, const uint4& a, uint32_t b0, uint32_t b1) {
    asm("mma.sync.aligned.m16n8k8.row.col.f32.tf32.tf32.f32 "
        "{%0,%1,%2,%3},{%4,%5,%6,%7},{%8,%9},{%0,%1,%2,%3};"
        : "+f"(d[0]), "+f"(d[1]), "+f"(d[2]), "+f"(d[3])
        : "r"(a.x), "r"(a.y), "r"(a.z), "r"(a.w), "r"(b0), "r"(b1));
}

// ------------------------------------------------------------------
// K1: NCHW -> [token][dim] transpose  (+ init g_best)
// ------------------------------------------------------------------
__global__ void k_transpose(const float* __restrict__ z) {
    __shared__ float tile[32][33];
    const int b = blockIdx.z;
    const int hwBase = blockIdx.x * 32;
    const int cBase  = blockIdx.y * 32;
    const int tx = threadIdx.x, ty = threadIdx.y;
    const int bid  = (blockIdx.z * gridDim.y + blockIdx.y) * gridDim.x + blockIdx.x;
    const int tlin = bid * 256 + ty * 32 + tx;
    if (tlin < N_TOK) g_best[tlin] = ~0ULL;
#pragma unroll
    for (int j = 0; j < 4; j++) {
        int c = cBase + ty + 8 * j;
        tile[ty + 8 * j][tx] = z[(b * EDIM + c) * HW + hwBase + tx];
    }
    __syncthreads();
#pragma unroll
    for (int j = 0; j < 4; j++) {
        int hw = hwBase + ty + 8 * j;
        g_zf[(b * HW + hw) * EDIM + cBase + tx] = tile[tx][ty + 8 * j];
    }
}

// ------------------------------------------------------------------
// K1b: emb -> tf32 fragment layout.
// slot = (ntile*16 + kpair)*32 + lane ; floats = emb[n][k0], [k0+4], [k0+8], [k0+12]
// with n = ntile*8 + lane/4, k0 = kpair*16 + lane%4   (m16n8k8 B frags, 2 ksteps)
// ------------------------------------------------------------------
__global__ void k_embfrag(const float* __restrict__ emb) {
    int slot = blockIdx.x * 256 + threadIdx.x;      // 0 .. 524287
    int lane  = slot & 31;
    int kpair = (slot >> 5) & 15;
    int ntile = slot >> 9;
    int n  = ntile * 8 + (lane >> 2);
    int k0 = kpair * 16 + (lane & 3);
    const float* e = emb + n * EDIM + k0;
    uint4 v;
    v.x = f2tf32(__ldg(e));
    v.y = f2tf32(__ldg(e + 4));
    v.z = f2tf32(__ldg(e + 8));
    v.w = f2tf32(__ldg(e + 12));
    g_embF[slot] = v;
}

// ------------------------------------------------------------------
// K2: tf32 mma.sync GEMM + argmin with epsilon-candidate exact rescore.
// CTA = 64 tokens; warp w owns codes [w*1024, (w+1)*1024).
// ------------------------------------------------------------------
__global__ void __launch_bounds__(256, 1) k_argmin_mma(const float* __restrict__ emb) {
    extern __shared__ char smraw[];
    uint4* As  = (uint4*)smraw;                  // [4 mt][32 ks][32 lane] = 64KB
    float* znS = (float*)(smraw + 65536);        // [64]

    const int tid = threadIdx.x;
    const int wid = tid >> 5, lane = tid & 31;
    const int c = lane & 3, g = lane >> 2;       // sublane / group
    const int rowBase = blockIdx.x * MT;

    // ---- stage A fragments (tf32) into smem ----
#pragma unroll
    for (int i = 0; i < 16; i++) {
        int slot = i * 256 + tid;                // 4096 slots
        int sl = slot & 31, ks = (slot >> 5) & 31, mt = slot >> 10;
        int r = rowBase + mt * 16 + (sl >> 2);
        int k = ks * 8 + (sl & 3);
        uint4 v;
        v.x = f2tf32(g_zf[r * EDIM + k]);
        v.y = f2tf32(g_zf[(r + 8) * EDIM + k]);
        v.z = f2tf32(g_zf[r * EDIM + k + 4]);
        v.w = f2tf32(g_zf[(r + 8) * EDIM + k + 4]);
        As[slot] = v;
    }
    // ---- zn: sequential fp32 fmaf (same chain as passing R2/R3 kernels) ----
    if (tid < MT) {
        const float4* zr = (const float4*)&g_zf[(rowBase + tid) * EDIM];
        float s = 0.f;
#pragma unroll 8
        for (int i = 0; i < 64; i++) {
            float4 a = zr[i];
            s = fmaf(a.x, a.x, s); s = fmaf(a.y, a.y, s);
            s = fmaf(a.z, a.z, s); s = fmaf(a.w, a.w, s);
        }
        znS[tid] = s;
    }
    __syncthreads();

    // per-lane-row state: slot = mt*2 + half; rows r = mt*16 + g (+8 for half=1)
    float best[8]; int cnt[8]; float zl[8]; int tok[8]; ull cbase[8];
#pragma unroll
    for (int mt = 0; mt < 4; mt++)
#pragma unroll
        for (int h = 0; h < 2; h++) {
            int s = mt * 2 + h;
            int t = rowBase + mt * 16 + g + h * 8;
            tok[s] = t;
            zl[s]  = znS[mt * 16 + g + h * 8];
            best[s] = __int_as_float(0x7f800000);
            cnt[s] = 0;
            cbase[s] = (ull)(((t * 8 + wid) * 4 + c) * CAP);
        }

    const int ntileW = wid * (WN / 8);           // warp's first ntile

#pragma unroll 1
    for (int ch = 0; ch < NCHUNK; ch++) {
        const int nt0 = ntileW + ch * 4;
        float acc[4][4][4];
#pragma unroll
        for (int mt = 0; mt < 4; mt++)
#pragma unroll
            for (int j = 0; j < 4; j++)
#pragma unroll
                for (int q = 0; q < 4; q++) acc[mt][j][q] = 0.f;

#pragma unroll 1
        for (int kp = 0; kp < KPAIRS; kp++) {
            uint4 bf[4];
#pragma unroll
            for (int j = 0; j < 4; j++)
                bf[j] = g_embF[((nt0 + j) * KPAIRS + kp) * 32 + lane];
            uint4 af[4][2];
#pragma unroll
            for (int mt = 0; mt < 4; mt++) {
                af[mt][0] = As[(mt * 32 + 2 * kp) * 32 + lane];
                af[mt][1] = As[(mt * 32 + 2 * kp + 1) * 32 + lane];
            }
#pragma unroll
            for (int mt = 0; mt < 4; mt++)
#pragma unroll
                for (int j = 0; j < 4; j++) {
                    mma_tf32(acc[mt][j], af[mt][0], bf[j].x, bf[j].y);
                    mma_tf32(acc[mt][j], af[mt][1], bf[j].z, bf[j].w);
                }
        }

        // epilogue: score = fmaf(-2, dot, zn); append candidates <= best+EPS
#pragma unroll
        for (int mt = 0; mt < 4; mt++)
#pragma unroll
            for (int j = 0; j < 4; j++) {
                const int colB = (nt0 + j) * 8 + 2 * c;
#pragma unroll
                for (int q = 0; q < 4; q++) {
                    const int s   = mt * 2 + (q >> 1);
                    const int col = colB + (q & 1);
                    float sc = fmaf(-2.0f, acc[mt][j][q], zl[s]);
                    if (sc <= best[s] + EPS) {
                        int w = cnt[s] < CAP ? cnt[s] : CAP - 1;
                        g_cand[cbase[s] + w] = ((ull)__float_as_uint(sc) << 32) | (unsigned)col;
                        cnt[s] = w + 1;
                        best[s] = fminf(best[s], sc);
                    }
                }
            }
    }

    // ---- filter + exact fp32 rescore + packed atomicMin ----
#pragma unroll 1
    for (int s = 0; s < 8; s++) {
        float bm = best[s];
        bm = fminf(bm, __shfl_xor_sync(0xFFFFFFFF, bm, 1));
        bm = fminf(bm, __shfl_xor_sync(0xFFFFFFFF, bm, 2));
        const float thr = bm + EPS;
        const int t = tok[s];
        const float4* zr = (const float4*)&g_zf[t * EDIM];
        ull bp = ~0ULL;
        for (int i = 0; i < cnt[s]; i++) {
            ull e = g_cand[cbase[s] + i];
            float ascore = __uint_as_float((uint32_t)(e >> 32));
            if (ascore > thr) continue;
            int col = (int)(e & 0xFFFFFFFF);
            const float4* er = (const float4*)&emb[col * EDIM];
            float dot = 0.f;
#pragma unroll 8
            for (int k = 0; k < 64; k++) {
                float4 a = zr[k], ev = er[k];
                dot = fmaf(a.x, ev.x, dot); dot = fmaf(a.y, ev.y, dot);
                dot = fmaf(a.z, ev.z, dot); dot = fmaf(a.w, ev.w, dot);
            }
            float sc = fmaf(-2.0f, dot, zl[s]);
            ull pk = ((ull)__float_as_uint(sc) << 32) | (unsigned)col;
            bp = pk < bp ? pk : bp;
        }
        ull o;
        o = __shfl_xor_sync(0xFFFFFFFF, bp, 1); bp = o < bp ? o : bp;
        o = __shfl_xor_sync(0xFFFFFFFF, bp, 2); bp = o < bp ? o : bp;
        if (c == 0) atomicMin(&g_best[t], bp);
    }
}

// ------------------------------------------------------------------
// K3: gather z_q -> NCHW output with reference ST rounding + MSE partials
// ------------------------------------------------------------------
__global__ void k_gather(const float* __restrict__ emb,
                         const float* __restrict__ z,
                         float* __restrict__ out) {
    const int c = blockIdx.x;
    const int b = blockIdx.y;
    const int tid = threadIdx.x;
    float lsum = 0.f;
#pragma unroll
    for (int u = 0; u < 4; u++) {
        int hw = u * 256 + tid;
        int n  = b * HW + hw;
        int k  = (int)(g_best[n] & 0xFFFFFFFF);
        float e  = __ldg(&emb[k * EDIM + c]);
        float zv = z[(b * EDIM + c) * HW + hw];
        float d  = e - zv;
        out[(b * EDIM + c) * HW + hw] = zv + d;   // straight-through rounding like ref
        lsum = fmaf(d, d, lsum);
    }
    __shared__ float red[256];
    red[tid] = lsum;
    __syncthreads();
    for (int s = 128; s > 0; s >>= 1) {
        if (tid < s) red[tid] += red[tid + s];
        __syncthreads();
    }
    if (tid == 0) g_msePart[b * 256 + c] = red[0];
}

// ------------------------------------------------------------------
// K4: losses, idx->float, histogram, perplexity
// ------------------------------------------------------------------
__global__ void k_finalize(float* __restrict__ out) {
    __shared__ int   counts[NE];
    __shared__ float redf[256];
    __shared__ float mseS[BATCH];
    const int tid = threadIdx.x;

    for (int i = tid; i < NE; i += 256) counts[i] = 0;
    __syncthreads();

    for (int i = tid; i < N_TOK; i += 256) {
        int k = (int)(g_best[i] & 0xFFFFFFFF);
        out[2097160 + i] = (float)k;
        atomicAdd(&counts[k], 1);
    }

    for (int b = 0; b < BATCH; b++) {
        redf[tid] = g_msePart[b * 256 + tid];
        __syncthreads();
        for (int s = 128; s > 0; s >>= 1) {
            if (tid < s) redf[tid] += redf[tid + s];
            __syncthreads();
        }
        if (tid == 0) mseS[b] = redf[0];
        __syncthreads();
    }

    if (tid < BATCH) {
        float m = mseS[tid] * (1.0f / 262144.0f);
        out[2097152 + tid] = m + 0.25f * m;
    }
    if (tid == 0) {
        float tot = 0.f;
        for (int b = 0; b < BATCH; b++) tot += mseS[b] * (1.0f / 262144.0f);
        float cm = tot * (1.0f / 8.0f);
        out[2105352] = cm;
        out[2105353] = 0.25f * cm;
    }
    __syncthreads();

    float ps = 0.f;
    for (int i = tid; i < NE; i += 256) {
        float p = (float)counts[i] * (1.0f / 8192.0f);
        ps += p * logf(p + 1e-10f);
    }
    redf[tid] = ps;
    __syncthreads();
    for (int s = 128; s > 0; s >>= 1) {
        if (tid < s) redf[tid] += redf[tid + s];
        __syncthreads();
    }
    if (tid == 0) out[2105354] = expf(-redf[0]);
}

// ------------------------------------------------------------------
extern "C" void kernel_launch(void* const* d_in, const int* in_sizes, int n_in,
                              void* d_out, int out_size) {
    const float* z   = (const float*)d_in[0];   // [8,256,32,32]
    const float* emb = (const float*)d_in[1];   // [8192,256]
    float* out = (float*)d_out;

    const int smemBytes = 65536 + 256;
    cudaFuncSetAttribute(k_argmin_mma, cudaFuncAttributeMaxDynamicSharedMemorySize, smemBytes);

    dim3 tb(32, 8);
    dim3 tg(HW / 32, EDIM / 32, BATCH);
    k_transpose<<<tg, tb>>>(z);

    k_embfrag<<<(NE / 8 * KPAIRS * 32) / 256, 256>>>(emb);

    k_argmin_mma<<<N_TOK / MT, 256, smemBytes>>>(emb);

    dim3 gg(EDIM, BATCH);
    k_gather<<<gg, 256>>>(emb, z, out);

    k_finalize<<<1, 256>>>(out);
}

// round 6
// speedup vs baseline: 4.2803x; 1.3312x over previous
#include <cuda_runtime.h>
#include <cuda_fp16.h>
#include <math.h>
#include <stdint.h>

#define N_TOK   8192
#define EDIM    256
#define NE      8192
#define BATCH   8
#define HW      1024

#define MT      64                  // tokens per CTA -> 128 CTAs
#define WN      1024                // codes per warp (8 warps disjoint)
#define NCHUNK  32                  // 4-ntile chunks per warp
#define KP      8                   // k-pairs (2 x k16 steps each) covering EDIM=256
#define SCALE   16384.0f            // 2^14 pre-scale for emb -> fp16 normal range
#define EPS_D   3.0f                // scaled-dot epsilon (1.8e-4 unscaled, ~15x err bound)
#define CAP     32

typedef unsigned long long ull;

// ---- scratch (static device globals; no allocation) ----
__device__ __align__(16) float g_zf[N_TOK * EDIM];           // z [token][dim]
__device__ __align__(16) uint4 g_embF[NE / 8 * KP * 32];     // emb*2^14 fp16 frag layout (4MB)
__device__ ull   g_cand[N_TOK * 8 * 4 * CAP];                // (dotBits<<32)|idx appends
__device__ ull   g_best[N_TOK];                              // packed exact best
__device__ float g_msePart[BATCH * 256];

__device__ __forceinline__ uint32_t packh2(float a, float b) {
    __half2 h = __floats2half2_rn(a, b);
    return *reinterpret_cast<uint32_t*>(&h);
}
__device__ __forceinline__ void mma_f16(float* d, const uint4& a, uint32_t b0, uint32_t b1) {
    asm("mma.sync.aligned.m16n8k16.row.col.f32.f16.f16.f32 "
        "{%0,%1,%2,%3},{%4,%5,%6,%7},{%8,%9},{%0,%1,%2,%3};"
        : "+f"(d[0]), "+f"(d[1]), "+f"(d[2]), "+f"(d[3])
        : "r"(a.x), "r"(a.y), "r"(a.z), "r"(a.w), "r"(b0), "r"(b1));
}

// ------------------------------------------------------------------
// K1: NCHW -> [token][dim] transpose  (+ init g_best)
// ------------------------------------------------------------------
__global__ void k_transpose(const float* __restrict__ z) {
    __shared__ float tile[32][33];
    const int b = blockIdx.z;
    const int hwBase = blockIdx.x * 32;
    const int cBase  = blockIdx.y * 32;
    const int tx = threadIdx.x, ty = threadIdx.y;
    const int bid  = (blockIdx.z * gridDim.y + blockIdx.y) * gridDim.x + blockIdx.x;
    const int tlin = bid * 256 + ty * 32 + tx;
    if (tlin < N_TOK) g_best[tlin] = ~0ULL;
#pragma unroll
    for (int j = 0; j < 4; j++) {
        int c = cBase + ty + 8 * j;
        tile[ty + 8 * j][tx] = z[(b * EDIM + c) * HW + hwBase + tx];
    }
    __syncthreads();
#pragma unroll
    for (int j = 0; j < 4; j++) {
        int hw = hwBase + ty + 8 * j;
        g_zf[(b * HW + hw) * EDIM + cBase + tx] = tile[tx][ty + 8 * j];
    }
}

// ------------------------------------------------------------------
// K1b: emb -> scaled fp16 fragment layout (m16n8k16 B frags, 2 ksteps/uint4).
// slot = (ntile*KP + kp)*32 + lane; n = ntile*8 + lane/4; kb = kp*32 + (lane%4)*2
//   x={e[n][kb],e[n][kb+1]}  y={+8,+9}  z={+16,+17}  w={+24,+25}   (all * 2^14)
// ------------------------------------------------------------------
__global__ void k_embfrag(const float* __restrict__ emb) {
    int slot = blockIdx.x * 256 + threadIdx.x;      // 0 .. 262143
    int lane  = slot & 31;
    int kp    = (slot >> 5) & (KP - 1);
    int ntile = slot >> 8;
    int n  = ntile * 8 + (lane >> 2);
    int kb = kp * 32 + (lane & 3) * 2;
    const float* e = emb + n * EDIM + kb;
    uint4 v;
    v.x = packh2(__ldg(e)      * SCALE, __ldg(e + 1)  * SCALE);
    v.y = packh2(__ldg(e + 8)  * SCALE, __ldg(e + 9)  * SCALE);
    v.z = packh2(__ldg(e + 16) * SCALE, __ldg(e + 17) * SCALE);
    v.w = packh2(__ldg(e + 24) * SCALE, __ldg(e + 25) * SCALE);
    g_embF[slot] = v;
}

// ------------------------------------------------------------------
// K2: fp16 mma.sync GEMM (ranking by max scaled dot) + exact fp32 rescore.
// CTA = 64 tokens; warp w owns codes [w*1024, (w+1)*1024).
// ------------------------------------------------------------------
__global__ void __launch_bounds__(256, 1) k_argmin_mma(const float* __restrict__ emb) {
    __shared__ uint4 As[4 * 16 * 32];            // A frags: [mt][kstep][lane], 32KB
    __shared__ float znS[MT];

    const int tid = threadIdx.x;
    const int wid = tid >> 5, lane = tid & 31;
    const int c = lane & 3, g = lane >> 2;
    const int rowBase = blockIdx.x * MT;

    // ---- stage A fragments (fp16, z unscaled) into smem ----
#pragma unroll
    for (int i = 0; i < 8; i++) {
        int slot = i * 256 + tid;                // 2048 slots
        int sl = slot & 31, ks = (slot >> 5) & 15, mt = slot >> 9;
        int r0 = rowBase + mt * 16 + (sl >> 2);
        int k  = ks * 16 + (sl & 3) * 2;
        const float* z0 = &g_zf[r0 * EDIM + k];
        const float* z1 = &g_zf[(r0 + 8) * EDIM + k];
        uint4 v;
        v.x = packh2(z0[0], z0[1]);
        v.y = packh2(z1[0], z1[1]);
        v.z = packh2(z0[8], z0[9]);
        v.w = packh2(z1[8], z1[9]);
        As[slot] = v;
    }
    // ---- zn: sequential fp32 fmaf (matches validated rescore chain) ----
    if (tid < MT) {
        const float4* zr = (const float4*)&g_zf[(rowBase + tid) * EDIM];
        float s = 0.f;
#pragma unroll 8
        for (int i = 0; i < 64; i++) {
            float4 a = zr[i];
            s = fmaf(a.x, a.x, s); s = fmaf(a.y, a.y, s);
            s = fmaf(a.z, a.z, s); s = fmaf(a.w, a.w, s);
        }
        znS[tid] = s;
    }
    __syncthreads();

    // per-lane-row state: slot s = mt*2 + half; rows = mt*16 + g (+8)
    float bestD[8]; int cnt[8]; float zl[8]; int tok[8]; ull cbase[8];
#pragma unroll
    for (int mt = 0; mt < 4; mt++)
#pragma unroll
        for (int h = 0; h < 2; h++) {
            int s = mt * 2 + h;
            int t = rowBase + mt * 16 + g + h * 8;
            tok[s] = t;
            zl[s]  = znS[mt * 16 + g + h * 8];
            bestD[s] = -__int_as_float(0x7f800000);
            cnt[s] = 0;
            cbase[s] = (ull)(((t * 8 + wid) * 4 + c) * CAP);
        }

    const int ntileW = wid * (WN / 8);

#pragma unroll 1
    for (int ch = 0; ch < NCHUNK; ch++) {
        const int nt0 = ntileW + ch * 4;
        float acc[4][4][4];
#pragma unroll
        for (int mt = 0; mt < 4; mt++)
#pragma unroll
            for (int j = 0; j < 4; j++)
#pragma unroll
                for (int q = 0; q < 4; q++) acc[mt][j][q] = 0.f;

#pragma unroll
        for (int kp = 0; kp < KP; kp++) {
            uint4 bf[4];
#pragma unroll
            for (int j = 0; j < 4; j++)
                bf[j] = __ldg(&g_embF[((nt0 + j) * KP + kp) * 32 + lane]);
            uint4 af[4][2];
#pragma unroll
            for (int mt = 0; mt < 4; mt++) {
                af[mt][0] = As[(mt * 16 + 2 * kp) * 32 + lane];
                af[mt][1] = As[(mt * 16 + 2 * kp + 1) * 32 + lane];
            }
#pragma unroll
            for (int mt = 0; mt < 4; mt++)
#pragma unroll
                for (int j = 0; j < 4; j++) {
                    mma_f16(acc[mt][j], af[mt][0], bf[j].x, bf[j].y);
                    mma_f16(acc[mt][j], af[mt][1], bf[j].z, bf[j].w);
                }
        }

        // epilogue: rank by scaled dot (max); append candidates >= best - EPS_D
#pragma unroll
        for (int mt = 0; mt < 4; mt++)
#pragma unroll
            for (int j = 0; j < 4; j++) {
                const int colB = (nt0 + j) * 8 + 2 * c;
#pragma unroll
                for (int q = 0; q < 4; q++) {
                    const int s   = mt * 2 + (q >> 1);
                    const int col = colB + (q & 1);
                    float d = acc[mt][j][q];
                    if (d >= bestD[s] - EPS_D) {
                        int w = cnt[s] < CAP ? cnt[s] : CAP - 1;
                        g_cand[cbase[s] + w] = ((ull)__float_as_uint(d) << 32) | (unsigned)col;
                        cnt[s] = w + 1;
                        bestD[s] = fmaxf(bestD[s], d);
                    }
                }
            }
    }

    // ---- filter + exact fp32 rescore + packed atomicMin ----
#pragma unroll 1
    for (int s = 0; s < 8; s++) {
        float bm = bestD[s];
        bm = fmaxf(bm, __shfl_xor_sync(0xFFFFFFFF, bm, 1));
        bm = fmaxf(bm, __shfl_xor_sync(0xFFFFFFFF, bm, 2));
        const float thr = bm - EPS_D;
        const int t = tok[s];
        const float4* zr = (const float4*)&g_zf[t * EDIM];
        ull bp = ~0ULL;
        for (int i = 0; i < cnt[s]; i++) {
            ull e = g_cand[cbase[s] + i];
            float ad = __uint_as_float((uint32_t)(e >> 32));
            if (ad < thr) continue;
            int col = (int)(e & 0xFFFFFFFF);
            const float4* er = (const float4*)&emb[col * EDIM];
            float dot = 0.f;
#pragma unroll 8
            for (int k = 0; k < 64; k++) {
                float4 a = zr[k], ev = er[k];
                dot = fmaf(a.x, ev.x, dot); dot = fmaf(a.y, ev.y, dot);
                dot = fmaf(a.z, ev.z, dot); dot = fmaf(a.w, ev.w, dot);
            }
            float sc = fmaf(-2.0f, dot, zl[s]);      // exact reference-order score
            ull pk = ((ull)__float_as_uint(sc) << 32) | (unsigned)col;
            bp = pk < bp ? pk : bp;
        }
        ull o;
        o = __shfl_xor_sync(0xFFFFFFFF, bp, 1); bp = o < bp ? o : bp;
        o = __shfl_xor_sync(0xFFFFFFFF, bp, 2); bp = o < bp ? o : bp;
        if (c == 0) atomicMin(&g_best[t], bp);
    }
}

// ------------------------------------------------------------------
// K3: gather z_q -> NCHW output with reference ST rounding + MSE partials
// ------------------------------------------------------------------
__global__ void k_gather(const float* __restrict__ emb,
                         const float* __restrict__ z,
                         float* __restrict__ out) {
    const int c = blockIdx.x;
    const int b = blockIdx.y;
    const int tid = threadIdx.x;
    float lsum = 0.f;
#pragma unroll
    for (int u = 0; u < 4; u++) {
        int hw = u * 256 + tid;
        int n  = b * HW + hw;
        int k  = (int)(g_best[n] & 0xFFFFFFFF);
        float e  = __ldg(&emb[k * EDIM + c]);
        float zv = z[(b * EDIM + c) * HW + hw];
        float d  = e - zv;
        out[(b * EDIM + c) * HW + hw] = zv + d;   // straight-through rounding like ref
        lsum = fmaf(d, d, lsum);
    }
    __shared__ float red[256];
    red[tid] = lsum;
    __syncthreads();
    for (int s = 128; s > 0; s >>= 1) {
        if (tid < s) red[tid] += red[tid + s];
        __syncthreads();
    }
    if (tid == 0) g_msePart[b * 256 + c] = red[0];
}

// ------------------------------------------------------------------
// K4: losses, idx->float, histogram, perplexity (1024 threads)
// ------------------------------------------------------------------
__global__ void k_finalize(float* __restrict__ out) {
    __shared__ int   counts[NE];
    __shared__ float redf[1024];
    __shared__ float mseS[BATCH];
    const int tid = threadIdx.x;

    for (int i = tid; i < NE; i += 1024) counts[i] = 0;
    __syncthreads();

    for (int i = tid; i < N_TOK; i += 1024) {
        int k = (int)(g_best[i] & 0xFFFFFFFF);
        out[2097160 + i] = (float)k;
        atomicAdd(&counts[k], 1);
    }

    // per-batch MSE: 128 threads per batch
    {
        const int b = tid >> 7, i = tid & 127;
        redf[tid] = g_msePart[b * 256 + i] + g_msePart[b * 256 + 128 + i];
        __syncthreads();
        for (int s = 64; s > 0; s >>= 1) {
            if (i < s) redf[tid] += redf[tid + s];
            __syncthreads();
        }
        if (i == 0) mseS[b] = redf[tid];
        __syncthreads();
    }

    if (tid < BATCH) {
        float m = mseS[tid] * (1.0f / 262144.0f);
        out[2097152 + tid] = m + 0.25f * m;
    }
    if (tid == 0) {
        float tot = 0.f;
        for (int b = 0; b < BATCH; b++) tot += mseS[b] * (1.0f / 262144.0f);
        float cm = tot * (1.0f / 8.0f);
        out[2105352] = cm;
        out[2105353] = 0.25f * cm;
    }
    __syncthreads();

    float ps = 0.f;
    for (int i = tid; i < NE; i += 1024) {
        float p = (float)counts[i] * (1.0f / 8192.0f);
        ps += p * logf(p + 1e-10f);
    }
    redf[tid] = ps;
    __syncthreads();
    for (int s = 512; s > 0; s >>= 1) {
        if (tid < s) redf[tid] += redf[tid + s];
        __syncthreads();
    }
    if (tid == 0) out[2105354] = expf(-redf[0]);
}

// ------------------------------------------------------------------
extern "C" void kernel_launch(void* const* d_in, const int* in_sizes, int n_in,
                              void* d_out, int out_size) {
    const float* z   = (const float*)d_in[0];   // [8,256,32,32]
    const float* emb = (const float*)d_in[1];   // [8192,256]
    float* out = (float*)d_out;

    dim3 tb(32, 8);
    dim3 tg(HW / 32, EDIM / 32, BATCH);
    k_transpose<<<tg, tb>>>(z);

    k_embfrag<<<(NE / 8 * KP * 32) / 256, 256>>>(emb);

    k_argmin_mma<<<N_TOK / MT, 256>>>(emb);

    dim3 gg(EDIM, BATCH);
    k_gather<<<gg, 256>>>(emb, z, out);

    k_finalize<<<1, 1024>>>(out);
}

// round 7
// speedup vs baseline: 5.2421x; 1.2247x over previous
#include <cuda_runtime.h>
#include <cuda_fp16.h>
#include <math.h>
#include <stdint.h>

#define N_TOK   8192
#define EDIM    256
#define NE      8192
#define BATCH   8
#define HW      1024

#define MT      32                  // tokens per CTA -> 256 CTAs (2 CTAs/SM)
#define WN      1024                // codes per warp (8 warps disjoint)
#define NCHUNK  32                  // 4-ntile chunks per warp
#define KP      8                   // k-pairs (2 x k16 steps each) covering EDIM=256
#define SCALE   16384.0f            // 2^14 pre-scale for emb -> fp16 normal range
#define EPS_D   3.0f                // scaled-dot epsilon (1.8e-4 unscaled)
#define CAP     32

typedef unsigned long long ull;

// ---- scratch (static device globals; no allocation) ----
__device__ __align__(16) float g_zf[N_TOK * EDIM];           // z [token][dim]
__device__ __align__(16) uint4 g_embF[NE / 8 * KP * 32];     // emb*2^14 fp16 frag layout (4MB)
__device__ ull   g_cand[N_TOK * 8 * 4 * CAP];                // (dotBits<<32)|idx appends
__device__ ull   g_best[N_TOK];                              // packed exact best
__device__ float g_msePart[BATCH * 256];

__device__ __forceinline__ uint32_t packh2(float a, float b) {
    __half2 h = __floats2half2_rn(a, b);
    return *reinterpret_cast<uint32_t*>(&h);
}
__device__ __forceinline__ void mma_f16(float* d, const uint4& a, uint32_t b0, uint32_t b1) {
    asm("mma.sync.aligned.m16n8k16.row.col.f32.f16.f16.f32 "
        "{%0,%1,%2,%3},{%4,%5,%6,%7},{%8,%9},{%0,%1,%2,%3};"
        : "+f"(d[0]), "+f"(d[1]), "+f"(d[2]), "+f"(d[3])
        : "r"(a.x), "r"(a.y), "r"(a.z), "r"(a.w), "r"(b0), "r"(b1));
}

// ------------------------------------------------------------------
// K1: NCHW -> [token][dim] transpose  (+ init g_best)
// ------------------------------------------------------------------
__global__ void k_transpose(const float* __restrict__ z) {
    __shared__ float tile[32][33];
    const int b = blockIdx.z;
    const int hwBase = blockIdx.x * 32;
    const int cBase  = blockIdx.y * 32;
    const int tx = threadIdx.x, ty = threadIdx.y;
    const int bid  = (blockIdx.z * gridDim.y + blockIdx.y) * gridDim.x + blockIdx.x;
    const int tlin = bid * 256 + ty * 32 + tx;
    if (tlin < N_TOK) g_best[tlin] = ~0ULL;
#pragma unroll
    for (int j = 0; j < 4; j++) {
        int c = cBase + ty + 8 * j;
        tile[ty + 8 * j][tx] = z[(b * EDIM + c) * HW + hwBase + tx];
    }
    __syncthreads();
#pragma unroll
    for (int j = 0; j < 4; j++) {
        int hw = hwBase + ty + 8 * j;
        g_zf[(b * HW + hw) * EDIM + cBase + tx] = tile[tx][ty + 8 * j];
    }
}

// ------------------------------------------------------------------
// K1b: emb -> scaled fp16 fragment layout (m16n8k16 B frags).
// ------------------------------------------------------------------
__global__ void k_embfrag(const float* __restrict__ emb) {
    int slot = blockIdx.x * 256 + threadIdx.x;      // 0 .. 262143
    int lane  = slot & 31;
    int kp    = (slot >> 5) & (KP - 1);
    int ntile = slot >> 8;
    int n  = ntile * 8 + (lane >> 2);
    int kb = kp * 32 + (lane & 3) * 2;
    const float* e = emb + n * EDIM + kb;
    uint4 v;
    v.x = packh2(__ldg(e)      * SCALE, __ldg(e + 1)  * SCALE);
    v.y = packh2(__ldg(e + 8)  * SCALE, __ldg(e + 9)  * SCALE);
    v.z = packh2(__ldg(e + 16) * SCALE, __ldg(e + 17) * SCALE);
    v.w = packh2(__ldg(e + 24) * SCALE, __ldg(e + 25) * SCALE);
    g_embF[slot] = v;
}

// ------------------------------------------------------------------
// K2: fp16 mma.sync GEMM (rank by max scaled dot) + exact fp32 rescore.
// CTA = 32 tokens (2 m16 tiles); warp w owns codes [w*1024,(w+1)*1024).
// 2 CTAs/SM for latency hiding.
// ------------------------------------------------------------------
__global__ void __launch_bounds__(256, 2) k_argmin_mma(const float* __restrict__ emb) {
    __shared__ uint4 As[2 * 16 * 32];            // A frags: [mt][kstep][lane], 16KB
    __shared__ float znS[MT];

    const int tid = threadIdx.x;
    const int wid = tid >> 5, lane = tid & 31;
    const int c = lane & 3, g = lane >> 2;
    const int rowBase = blockIdx.x * MT;

    // ---- stage A fragments (fp16, z unscaled) into smem ----
#pragma unroll
    for (int i = 0; i < 4; i++) {
        int slot = i * 256 + tid;                // 1024 slots
        int sl = slot & 31, ks = (slot >> 5) & 15, mt = slot >> 9;
        int r0 = rowBase + mt * 16 + (sl >> 2);
        int k  = ks * 16 + (sl & 3) * 2;
        const float* z0 = &g_zf[r0 * EDIM + k];
        const float* z1 = &g_zf[(r0 + 8) * EDIM + k];
        uint4 v;
        v.x = packh2(z0[0], z0[1]);
        v.y = packh2(z1[0], z1[1]);
        v.z = packh2(z0[8], z0[9]);
        v.w = packh2(z1[8], z1[9]);
        As[slot] = v;
    }
    // ---- zn: sequential fp32 fmaf (matches validated rescore chain) ----
    if (tid < MT) {
        const float4* zr = (const float4*)&g_zf[(rowBase + tid) * EDIM];
        float s = 0.f;
#pragma unroll 8
        for (int i = 0; i < 64; i++) {
            float4 a = zr[i];
            s = fmaf(a.x, a.x, s); s = fmaf(a.y, a.y, s);
            s = fmaf(a.z, a.z, s); s = fmaf(a.w, a.w, s);
        }
        znS[tid] = s;
    }
    __syncthreads();

    // per-lane-row state: slot s = mt*2 + half; rows = mt*16 + g (+8)
    float bestD[4]; int cnt[4]; float zl[4]; int tok[4]; ull cbase[4];
#pragma unroll
    for (int mt = 0; mt < 2; mt++)
#pragma unroll
        for (int h = 0; h < 2; h++) {
            int s = mt * 2 + h;
            int t = rowBase + mt * 16 + g + h * 8;
            tok[s] = t;
            zl[s]  = znS[mt * 16 + g + h * 8];
            bestD[s] = -__int_as_float(0x7f800000);
            cnt[s] = 0;
            cbase[s] = (ull)(((t * 8 + wid) * 4 + c) * CAP);
        }

    const int ntileW = wid * (WN / 8);

#pragma unroll 1
    for (int ch = 0; ch < NCHUNK; ch++) {
        const int nt0 = ntileW + ch * 4;
        float acc[2][4][4];
#pragma unroll
        for (int mt = 0; mt < 2; mt++)
#pragma unroll
            for (int j = 0; j < 4; j++)
#pragma unroll
                for (int q = 0; q < 4; q++) acc[mt][j][q] = 0.f;

#pragma unroll
        for (int kp = 0; kp < KP; kp++) {
            uint4 bf[4];
#pragma unroll
            for (int j = 0; j < 4; j++)
                bf[j] = __ldg(&g_embF[((nt0 + j) * KP + kp) * 32 + lane]);
            uint4 af[2][2];
#pragma unroll
            for (int mt = 0; mt < 2; mt++) {
                af[mt][0] = As[(mt * 16 + 2 * kp) * 32 + lane];
                af[mt][1] = As[(mt * 16 + 2 * kp + 1) * 32 + lane];
            }
#pragma unroll
            for (int mt = 0; mt < 2; mt++)
#pragma unroll
                for (int j = 0; j < 4; j++) {
                    mma_f16(acc[mt][j], af[mt][0], bf[j].x, bf[j].y);
                    mma_f16(acc[mt][j], af[mt][1], bf[j].z, bf[j].w);
                }
        }

        // epilogue: rank by scaled dot (max); append candidates >= best - EPS_D
#pragma unroll
        for (int mt = 0; mt < 2; mt++)
#pragma unroll
            for (int j = 0; j < 4; j++) {
                const int colB = (nt0 + j) * 8 + 2 * c;
#pragma unroll
                for (int q = 0; q < 4; q++) {
                    const int s   = mt * 2 + (q >> 1);
                    const int col = colB + (q & 1);
                    float d = acc[mt][j][q];
                    if (d >= bestD[s] - EPS_D) {
                        int w = cnt[s] < CAP ? cnt[s] : CAP - 1;
                        g_cand[cbase[s] + w] = ((ull)__float_as_uint(d) << 32) | (unsigned)col;
                        cnt[s] = w + 1;
                        bestD[s] = fmaxf(bestD[s], d);
                    }
                }
            }
    }

    // ---- filter + exact fp32 rescore + packed atomicMin ----
#pragma unroll 1
    for (int s = 0; s < 4; s++) {
        float bm = bestD[s];
        bm = fmaxf(bm, __shfl_xor_sync(0xFFFFFFFF, bm, 1));
        bm = fmaxf(bm, __shfl_xor_sync(0xFFFFFFFF, bm, 2));
        const float thr = bm - EPS_D;
        const int t = tok[s];
        const float4* zr = (const float4*)&g_zf[t * EDIM];
        ull bp = ~0ULL;
        for (int i = 0; i < cnt[s]; i++) {
            ull e = g_cand[cbase[s] + i];
            float ad = __uint_as_float((uint32_t)(e >> 32));
            if (ad < thr) continue;
            int col = (int)(e & 0xFFFFFFFF);
            const float4* er = (const float4*)&emb[col * EDIM];
            float dot = 0.f;
#pragma unroll 8
            for (int k = 0; k < 64; k++) {
                float4 a = zr[k], ev = er[k];
                dot = fmaf(a.x, ev.x, dot); dot = fmaf(a.y, ev.y, dot);
                dot = fmaf(a.z, ev.z, dot); dot = fmaf(a.w, ev.w, dot);
            }
            float sc = fmaf(-2.0f, dot, zl[s]);      // exact reference-order score
            ull pk = ((ull)__float_as_uint(sc) << 32) | (unsigned)col;
            bp = pk < bp ? pk : bp;
        }
        ull o;
        o = __shfl_xor_sync(0xFFFFFFFF, bp, 1); bp = o < bp ? o : bp;
        o = __shfl_xor_sync(0xFFFFFFFF, bp, 2); bp = o < bp ? o : bp;
        if (c == 0) atomicMin(&g_best[t], bp);
    }
}

// ------------------------------------------------------------------
// K3: gather z_q -> NCHW output with reference ST rounding + MSE partials
// ------------------------------------------------------------------
__global__ void k_gather(const float* __restrict__ emb,
                         const float* __restrict__ z,
                         float* __restrict__ out) {
    const int c = blockIdx.x;
    const int b = blockIdx.y;
    const int tid = threadIdx.x;
    float lsum = 0.f;
#pragma unroll
    for (int u = 0; u < 4; u++) {
        int hw = u * 256 + tid;
        int n  = b * HW + hw;
        int k  = (int)(g_best[n] & 0xFFFFFFFF);
        float e  = __ldg(&emb[k * EDIM + c]);
        float zv = z[(b * EDIM + c) * HW + hw];
        float d  = e - zv;
        out[(b * EDIM + c) * HW + hw] = zv + d;   // straight-through rounding like ref
        lsum = fmaf(d, d, lsum);
    }
    __shared__ float red[256];
    red[tid] = lsum;
    __syncthreads();
    for (int s = 128; s > 0; s >>= 1) {
        if (tid < s) red[tid] += red[tid + s];
        __syncthreads();
    }
    if (tid == 0) g_msePart[b * 256 + c] = red[0];
}

// ------------------------------------------------------------------
// K4: losses, idx->float, histogram, perplexity (1024 threads)
// ------------------------------------------------------------------
__global__ void k_finalize(float* __restrict__ out) {
    __shared__ int   counts[NE];
    __shared__ float redf[1024];
    __shared__ float mseS[BATCH];
    const int tid = threadIdx.x;

    for (int i = tid; i < NE; i += 1024) counts[i] = 0;
    __syncthreads();

    for (int i = tid; i < N_TOK; i += 1024) {
        int k = (int)(g_best[i] & 0xFFFFFFFF);
        out[2097160 + i] = (float)k;
        atomicAdd(&counts[k], 1);
    }

    {
        const int b = tid >> 7, i = tid & 127;
        redf[tid] = g_msePart[b * 256 + i] + g_msePart[b * 256 + 128 + i];
        __syncthreads();
        for (int s = 64; s > 0; s >>= 1) {
            if (i < s) redf[tid] += redf[tid + s];
            __syncthreads();
        }
        if (i == 0) mseS[b] = redf[tid];
        __syncthreads();
    }

    if (tid < BATCH) {
        float m = mseS[tid] * (1.0f / 262144.0f);
        out[2097152 + tid] = m + 0.25f * m;
    }
    if (tid == 0) {
        float tot = 0.f;
        for (int b = 0; b < BATCH; b++) tot += mseS[b] * (1.0f / 262144.0f);
        float cm = tot * (1.0f / 8.0f);
        out[2105352] = cm;
        out[2105353] = 0.25f * cm;
    }
    __syncthreads();

    float ps = 0.f;
    for (int i = tid; i < NE; i += 1024) {
        float p = (float)counts[i] * (1.0f / 8192.0f);
        ps += p * logf(p + 1e-10f);
    }
    redf[tid] = ps;
    __syncthreads();
    for (int s = 512; s > 0; s >>= 1) {
        if (tid < s) redf[tid] += redf[tid + s];
        __syncthreads();
    }
    if (tid == 0) out[2105354] = expf(-redf[0]);
}

// ------------------------------------------------------------------
extern "C" void kernel_launch(void* const* d_in, const int* in_sizes, int n_in,
                              void* d_out, int out_size) {
    const float* z   = (const float*)d_in[0];   // [8,256,32,32]
    const float* emb = (const float*)d_in[1];   // [8192,256]
    float* out = (float*)d_out;

    dim3 tb(32, 8);
    dim3 tg(HW / 32, EDIM / 32, BATCH);
    k_transpose<<<tg, tb>>>(z);

    k_embfrag<<<(NE / 8 * KP * 32) / 256, 256>>>(emb);

    k_argmin_mma<<<N_TOK / MT, 256>>>(emb);

    dim3 gg(EDIM, BATCH);
    k_gather<<<gg, 256>>>(emb, z, out);

    k_finalize<<<1, 1024>>>(out);
}

// round 8
// speedup vs baseline: 6.1592x; 1.1750x over previous
#include <cuda_runtime.h>
#include <cuda_fp16.h>
#include <math.h>
#include <stdint.h>

#define N_TOK   8192
#define NE      8192
#define EDIM    256
#define BATCH   8
#define HW      1024

#define MT      64                  // tokens per CTA (4 m16 tiles) -> 128 CTAs
#define KP      8                   // k-pairs (2 x k16 each) covering EDIM=256
#define NCH     64                  // chunks of 128 codes (16 ntiles)
#define SCALE   16384.0f            // 2^14 emb pre-scale for fp16
#define EPS_D   3.0f                // scaled-dot epsilon (1.8e-4 unscaled)
#define CAP     32

#define CHUNK_SLOTS 4096            // 16 ntiles * KP * 32 lanes (uint4 slots, 64KB)

typedef unsigned long long ull;

// ---- scratch (static device globals; no allocation) ----
__device__ __align__(16) float g_zf[N_TOK * EDIM];        // z [token][dim]
__device__ __align__(16) uint4 g_embF[NE / 8 * KP * 32];  // emb*2^14 fp16 frags (4MB)
__device__ ull   g_cand[N_TOK * 2 * 4 * CAP];             // (dotBits<<32)|idx appends
__device__ ull   g_best[N_TOK];
__device__ float g_msePart[BATCH * 256];

__device__ __forceinline__ uint32_t packh2(float a, float b) {
    __half2 h = __floats2half2_rn(a, b);
    return *reinterpret_cast<uint32_t*>(&h);
}
__device__ __forceinline__ void mma_f16(float* d, const uint4& a, uint32_t b0, uint32_t b1) {
    asm("mma.sync.aligned.m16n8k16.row.col.f32.f16.f16.f32 "
        "{%0,%1,%2,%3},{%4,%5,%6,%7},{%8,%9},{%0,%1,%2,%3};"
        : "+f"(d[0]), "+f"(d[1]), "+f"(d[2]), "+f"(d[3])
        : "r"(a.x), "r"(a.y), "r"(a.z), "r"(a.w), "r"(b0), "r"(b1));
}
__device__ __forceinline__ uint32_t smem_u32(const void* p) {
    uint32_t a;
    asm("{ .reg .u64 t; cvta.to.shared.u64 t, %1; cvt.u32.u64 %0, t; }" : "=r"(a) : "l"(p));
    return a;
}
__device__ __forceinline__ void cp16(uint32_t dst, const void* src) {
    asm volatile("cp.async.cg.shared.global [%0], [%1], 16;" :: "r"(dst), "l"(src) : "memory");
}

// ------------------------------------------------------------------
// K1: NCHW -> [token][dim] transpose  (+ init g_best)
// ------------------------------------------------------------------
__global__ void k_transpose(const float* __restrict__ z) {
    __shared__ float tile[32][33];
    const int b = blockIdx.z;
    const int hwBase = blockIdx.x * 32;
    const int cBase  = blockIdx.y * 32;
    const int tx = threadIdx.x, ty = threadIdx.y;
    const int bid  = (blockIdx.z * gridDim.y + blockIdx.y) * gridDim.x + blockIdx.x;
    const int tlin = bid * 256 + ty * 32 + tx;
    if (tlin < N_TOK) g_best[tlin] = ~0ULL;
#pragma unroll
    for (int j = 0; j < 4; j++) {
        int c = cBase + ty + 8 * j;
        tile[ty + 8 * j][tx] = z[(b * EDIM + c) * HW + hwBase + tx];
    }
    __syncthreads();
#pragma unroll
    for (int j = 0; j < 4; j++) {
        int hw = hwBase + ty + 8 * j;
        g_zf[(b * HW + hw) * EDIM + cBase + tx] = tile[tx][ty + 8 * j];
    }
}

// ------------------------------------------------------------------
// K1b: emb -> scaled fp16 fragment layout (m16n8k16 B frags).
// slot = (ntile*KP + kp)*32 + lane
// ------------------------------------------------------------------
__global__ void k_embfrag(const float* __restrict__ emb) {
    int slot = blockIdx.x * 256 + threadIdx.x;
    int lane  = slot & 31;
    int kp    = (slot >> 5) & (KP - 1);
    int ntile = slot >> 8;
    int n  = ntile * 8 + (lane >> 2);
    int kb = kp * 32 + (lane & 3) * 2;
    const float* e = emb + n * EDIM + kb;
    uint4 v;
    v.x = packh2(__ldg(e)      * SCALE, __ldg(e + 1)  * SCALE);
    v.y = packh2(__ldg(e + 8)  * SCALE, __ldg(e + 9)  * SCALE);
    v.z = packh2(__ldg(e + 16) * SCALE, __ldg(e + 17) * SCALE);
    v.w = packh2(__ldg(e + 24) * SCALE, __ldg(e + 25) * SCALE);
    g_embF[slot] = v;
}

// ------------------------------------------------------------------
// K2: fp16 mma GEMM, B staged through smem via cp.async double-buffer.
// CTA = 64 tokens; warp w: m-tile = w>>1, code-half = w&1 (8 ntiles/chunk).
// Rank by max scaled dot; exact fp32 rescore of epsilon-candidates.
// ------------------------------------------------------------------
__global__ void __launch_bounds__(256, 1) k_argmin_mma(const float* __restrict__ emb) {
    extern __shared__ uint4 Bs[];                 // [2][CHUNK_SLOTS] + znS tail
    float* znS = (float*)(Bs + 2 * CHUNK_SLOTS);  // [64]
    const uint32_t BsAddr = smem_u32(Bs);

    const int tid = threadIdx.x;
    const int wid = tid >> 5, lane = tid & 31;
    const int c = lane & 3, g = lane >> 2;
    const int mt = wid >> 1, half = wid & 1;
    const int rowBase = blockIdx.x * MT;
    const int r0 = rowBase + mt * 16 + g;         // token row (h=0); +8 for h=1

    // ---- zn for this CTA's tokens (validated sequential fmaf chain) ----
    if (tid < MT) {
        const float4* zr = (const float4*)&g_zf[(rowBase + tid) * EDIM];
        float s = 0.f;
#pragma unroll 8
        for (int i = 0; i < 64; i++) {
            float4 a = zr[i];
            s = fmaf(a.x, a.x, s); s = fmaf(a.y, a.y, s);
            s = fmaf(a.z, a.z, s); s = fmaf(a.w, a.w, s);
        }
        znS[tid] = s;
    }

    // ---- A fragments into registers (fp16, unscaled z) ----
    uint4 areg[16];
    {
        const float* z0 = &g_zf[r0 * EDIM];
        const float* z1 = &g_zf[(r0 + 8) * EDIM];
#pragma unroll
        for (int ks = 0; ks < 16; ks++) {
            int k = ks * 16 + c * 2;
            float2 a0 = *(const float2*)(z0 + k);
            float2 a1 = *(const float2*)(z1 + k);
            float2 b0 = *(const float2*)(z0 + k + 8);
            float2 b1 = *(const float2*)(z1 + k + 8);
            areg[ks].x = packh2(a0.x, a0.y);
            areg[ks].y = packh2(a1.x, a1.y);
            areg[ks].z = packh2(b0.x, b0.y);
            areg[ks].w = packh2(b1.x, b1.y);
        }
    }

    // ---- prefetch chunk 0 ----
#pragma unroll
    for (int it = 0; it < 16; it++) {
        int s = it * 256 + tid;
        cp16(BsAddr + s * 16, &g_embF[s]);
    }
    asm volatile("cp.async.commit_group;" ::: "memory");
    __syncthreads();

    // per-lane token state: h = 0 (row g), 1 (row g+8)
    float bestD[2]; int cnt[2]; float zl[2]; ull cbase[2];
#pragma unroll
    for (int h = 0; h < 2; h++) {
        int t = r0 + h * 8;
        zl[h] = znS[mt * 16 + g + h * 8];
        bestD[h] = -__int_as_float(0x7f800000);
        cnt[h] = 0;
        cbase[h] = (ull)(((t * 2 + half) * 4 + c) * CAP);
    }

    const int ntlBase = half * 8;

#pragma unroll 1
    for (int ch = 0; ch < NCH; ch++) {
        const int buf = ch & 1;
        if (ch + 1 < NCH) {                       // prefetch next chunk
            const uint4* src = &g_embF[(ch + 1) * CHUNK_SLOTS];
            const uint32_t dst = BsAddr + ((ch + 1) & 1) * (CHUNK_SLOTS * 16);
#pragma unroll
            for (int it = 0; it < 16; it++) {
                int s = it * 256 + tid;
                cp16(dst + s * 16, src + s);
            }
            asm volatile("cp.async.commit_group;" ::: "memory");
            asm volatile("cp.async.wait_group 1;" ::: "memory");
        } else {
            asm volatile("cp.async.wait_group 0;" ::: "memory");
        }
        __syncthreads();

        const uint4* Bp = Bs + buf * CHUNK_SLOTS + (ntlBase * 8) * 32 + lane;

        float acc[8][4];
#pragma unroll
        for (int j = 0; j < 8; j++)
#pragma unroll
            for (int q = 0; q < 4; q++) acc[j][q] = 0.f;

#pragma unroll
        for (int kp = 0; kp < KP; kp++) {
            const uint4 a0 = areg[2 * kp], a1 = areg[2 * kp + 1];
#pragma unroll
            for (int j = 0; j < 8; j++) {
                uint4 bf = Bp[(j * 8 + kp) * 32];
                mma_f16(acc[j], a0, bf.x, bf.y);
                mma_f16(acc[j], a1, bf.z, bf.w);
            }
        }
        __syncthreads();    // done reading buf before it is overwritten (ch+2)

        // epilogue: append candidates >= best - EPS_D (ascending code order)
#pragma unroll
        for (int j = 0; j < 8; j++) {
            const int colB = (ch * 16 + ntlBase + j) * 8 + 2 * c;
#pragma unroll
            for (int q = 0; q < 4; q++) {
                const int h   = q >> 1;
                const int col = colB + (q & 1);
                float d = acc[j][q];
                if (d >= bestD[h] - EPS_D) {
                    int w = cnt[h] < CAP ? cnt[h] : CAP - 1;
                    g_cand[cbase[h] + w] = ((ull)__float_as_uint(d) << 32) | (unsigned)col;
                    cnt[h] = w + 1;
                    bestD[h] = fmaxf(bestD[h], d);
                }
            }
        }
    }

    // ---- filter + exact fp32 rescore + packed atomicMin ----
#pragma unroll 1
    for (int h = 0; h < 2; h++) {
        float bm = bestD[h];
        bm = fmaxf(bm, __shfl_xor_sync(0xFFFFFFFF, bm, 1));
        bm = fmaxf(bm, __shfl_xor_sync(0xFFFFFFFF, bm, 2));
        const float thr = bm - EPS_D;
        const int t = r0 + h * 8;
        const float4* zr = (const float4*)&g_zf[t * EDIM];
        ull bp = ~0ULL;
        for (int i = 0; i < cnt[h]; i++) {
            ull e = g_cand[cbase[h] + i];
            float ad = __uint_as_float((uint32_t)(e >> 32));
            if (ad < thr) continue;
            int col = (int)(e & 0xFFFFFFFF);
            const float4* er = (const float4*)&emb[col * EDIM];
            float dot = 0.f;
#pragma unroll 8
            for (int k = 0; k < 64; k++) {
                float4 a = zr[k], ev = er[k];
                dot = fmaf(a.x, ev.x, dot); dot = fmaf(a.y, ev.y, dot);
                dot = fmaf(a.z, ev.z, dot); dot = fmaf(a.w, ev.w, dot);
            }
            float sc = fmaf(-2.0f, dot, zl[h]);   // exact reference-order score
            ull pk = ((ull)__float_as_uint(sc) << 32) | (unsigned)col;
            bp = pk < bp ? pk : bp;
        }
        ull o;
        o = __shfl_xor_sync(0xFFFFFFFF, bp, 1); bp = o < bp ? o : bp;
        o = __shfl_xor_sync(0xFFFFFFFF, bp, 2); bp = o < bp ? o : bp;
        if (c == 0) atomicMin(&g_best[t], bp);
    }
}

// ------------------------------------------------------------------
// K3: gather z_q -> NCHW output with reference ST rounding + MSE partials
// ------------------------------------------------------------------
__global__ void k_gather(const float* __restrict__ emb,
                         const float* __restrict__ z,
                         float* __restrict__ out) {
    const int c = blockIdx.x;
    const int b = blockIdx.y;
    const int tid = threadIdx.x;
    float lsum = 0.f;
#pragma unroll
    for (int u = 0; u < 4; u++) {
        int hw = u * 256 + tid;
        int n  = b * HW + hw;
        int k  = (int)(g_best[n] & 0xFFFFFFFF);
        float e  = __ldg(&emb[k * EDIM + c]);
        float zv = z[(b * EDIM + c) * HW + hw];
        float d  = e - zv;
        out[(b * EDIM + c) * HW + hw] = zv + d;
        lsum = fmaf(d, d, lsum);
    }
    __shared__ float red[256];
    red[tid] = lsum;
    __syncthreads();
    for (int s = 128; s > 0; s >>= 1) {
        if (tid < s) red[tid] += red[tid + s];
        __syncthreads();
    }
    if (tid == 0) g_msePart[b * 256 + c] = red[0];
}

// ------------------------------------------------------------------
// K4: losses, idx->float, histogram, perplexity (1024 threads)
// ------------------------------------------------------------------
__global__ void k_finalize(float* __restrict__ out) {
    __shared__ int   counts[NE];
    __shared__ float redf[1024];
    __shared__ float mseS[BATCH];
    const int tid = threadIdx.x;

    for (int i = tid; i < NE; i += 1024) counts[i] = 0;
    __syncthreads();

    for (int i = tid; i < N_TOK; i += 1024) {
        int k = (int)(g_best[i] & 0xFFFFFFFF);
        out[2097160 + i] = (float)k;
        atomicAdd(&counts[k], 1);
    }

    {
        const int b = tid >> 7, i = tid & 127;
        redf[tid] = g_msePart[b * 256 + i] + g_msePart[b * 256 + 128 + i];
        __syncthreads();
        for (int s = 64; s > 0; s >>= 1) {
            if (i < s) redf[tid] += redf[tid + s];
            __syncthreads();
        }
        if (i == 0) mseS[b] = redf[tid];
        __syncthreads();
    }

    if (tid < BATCH) {
        float m = mseS[tid] * (1.0f / 262144.0f);
        out[2097152 + tid] = m + 0.25f * m;
    }
    if (tid == 0) {
        float tot = 0.f;
        for (int b = 0; b < BATCH; b++) tot += mseS[b] * (1.0f / 262144.0f);
        float cm = tot * (1.0f / 8.0f);
        out[2105352] = cm;
        out[2105353] = 0.25f * cm;
    }
    __syncthreads();

    float ps = 0.f;
    for (int i = tid; i < NE; i += 1024) {
        float p = (float)counts[i] * (1.0f / 8192.0f);
        ps += p * logf(p + 1e-10f);
    }
    redf[tid] = ps;
    __syncthreads();
    for (int s = 512; s > 0; s >>= 1) {
        if (tid < s) redf[tid] += redf[tid + s];
        __syncthreads();
    }
    if (tid == 0) out[2105354] = expf(-redf[0]);
}

// ------------------------------------------------------------------
extern "C" void kernel_launch(void* const* d_in, const int* in_sizes, int n_in,
                              void* d_out, int out_size) {
    const float* z   = (const float*)d_in[0];   // [8,256,32,32]
    const float* emb = (const float*)d_in[1];   // [8192,256]
    float* out = (float*)d_out;

    const int smemBytes = 2 * CHUNK_SLOTS * 16 + 256;   // 128KB B double-buffer + znS
    cudaFuncSetAttribute(k_argmin_mma, cudaFuncAttributeMaxDynamicSharedMemorySize, smemBytes);

    dim3 tb(32, 8);
    dim3 tg(HW / 32, EDIM / 32, BATCH);
    k_transpose<<<tg, tb>>>(z);

    k_embfrag<<<(NE / 8 * KP * 32) / 256, 256>>>(emb);

    k_argmin_mma<<<N_TOK / MT, 256, smemBytes>>>(emb);

    dim3 gg(EDIM, BATCH);
    k_gather<<<gg, 256>>>(emb, z, out);

    k_finalize<<<1, 1024>>>(out);
}